// round 10
// baseline (speedup 1.0000x reference)
#include <cuda_runtime.h>
#include <cstdint>

// ---------------------------------------------------------------------------
// GCN layer on GB300 (plain compute_103 PTX -> legacy mma.sync tf32 path):
//   d[i]  = rsqrt(1 + #{j : A[i][j] > 1e-15})
//   g     = diag(d) @ (x @ W^T)                      [8192,256]
//   out   = relu( diag(d) @ (A @ g + g) )            [8192,256]
//   output buffer = [ out (8192*256 f32) | verbatim copy of A (8192^2 f32) ]
//
// K1: degrees only (A read once)
// K2: fp32 SIMT linear (exact); writes g_h exact + g_gT tf32-rounded with
//     16-group interleave (one LDS.128 in K3 serves two k-steps of B frags)
// K3: mma.sync m16n8k8 tf32 GEMM, 128x128 CTA tile, BK=64, 3-stage cp.async
//     pipe (227KB smem); A frags via ldmatrix.x4, raw-f32 A operands (HW
//     tf32 truncation), one barrier per 64-K chunk; verbatim A copy emitted
//     from staged smem tiles after the MMA block.
// ---------------------------------------------------------------------------

#define EPSV 1e-15f

static constexpr int NN = 8192;   // nodes
static constexpr int DF = 256;    // feature dim (in == out)

// K3 tiling
static constexpr int BK = 64;                        // K elems per stage
static constexpr int NCHUNK = NN / BK;               // 128
static constexpr int STAGES = 3;
static constexpr int LDSA = 68;   // A smem row stride (floats): ldmatrix conflict-free (4*68%32==16)
static constexpr int LDSB = 80;   // B smem row stride (floats): LDS.128 conflict-free (80%32==16)
static constexpr int A_TILE_FLOATS = 128 * LDSA;     // 8704
static constexpr int B_TILE_FLOATS = 128 * LDSB;     // 10240
static constexpr int STAGE_FLOATS  = A_TILE_FLOATS + B_TILE_FLOATS;  // 18944
static constexpr int SMEM_BYTES    = STAGES * STAGE_FLOATS * 4;      // 227328

// K2 smem stride
static constexpr int LDS2 = 36;

// scratch (static device arrays: allocation-free)
__device__ __align__(128) float g_gT[(size_t)DF * NN];  // tf32-rounded, 16-group interleaved g^T
__device__ __align__(128) float g_h [(size_t)NN * DF];  // exact g [8192][256]
__device__ float g_d[NN];

// ---------------------------------------------------------------------------
// PTX helpers (plain sm_80+ PTX only: safe for non-'a' target)
// ---------------------------------------------------------------------------
__device__ __forceinline__ uint32_t smem_u32(const void* p) {
    uint32_t a;
    asm("{ .reg .u64 t; cvta.to.shared.u64 t, %1; cvt.u32.u64 %0, t; }"
        : "=r"(a) : "l"(p));
    return a;
}

__device__ __forceinline__ void cp_async16(uint32_t dst, const void* src) {
    asm volatile("cp.async.cg.shared.global [%0], [%1], 16;"
                 :: "r"(dst), "l"(src));
}
#define CP_COMMIT() asm volatile("cp.async.commit_group;" ::: "memory")
#define CP_WAIT1()  asm volatile("cp.async.wait_group 1;" ::: "memory")

__device__ __forceinline__ uint32_t f2tf32(float f) {
    uint32_t r;
    asm("cvt.rna.tf32.f32 %0, %1;" : "=r"(r) : "f"(f));
    return r;
}

// ldmatrix.x4: four 8x8 b16 tiles == one 16x8 tf32 A fragment {a0,a1,a2,a3}
__device__ __forceinline__ void ldsm_x4(uint32_t* r, uint32_t addr) {
    asm volatile("ldmatrix.sync.aligned.m8n8.x4.shared.b16 {%0,%1,%2,%3}, [%4];"
                 : "=r"(r[0]), "=r"(r[1]), "=r"(r[2]), "=r"(r[3])
                 : "r"(addr));
}

__device__ __forceinline__ void mma_tf32(float* d, const uint32_t* a,
                                         const uint32_t* b) {
    asm volatile(
        "mma.sync.aligned.m16n8k8.row.col.f32.tf32.tf32.f32 "
        "{%0,%1,%2,%3}, {%4,%5,%6,%7}, {%8,%9}, {%0,%1,%2,%3};"
        : "+f"(d[0]), "+f"(d[1]), "+f"(d[2]), "+f"(d[3])
        : "r"(a[0]), "r"(a[1]), "r"(a[2]), "r"(a[3]),
          "r"(b[0]), "r"(b[1]));
}

// ---------------------------------------------------------------------------
// K1: degrees only. One block per row: 256 threads x 8 float4 (read 256 MB).
// ---------------------------------------------------------------------------
__global__ void __launch_bounds__(256) k1_deg(const float* __restrict__ A) {
    int row = blockIdx.x;
    const float4* src = reinterpret_cast<const float4*>(A + (size_t)row * NN);
    int cnt = 0;
    #pragma unroll
    for (int i = 0; i < 8; i++) {
        float4 v = src[threadIdx.x + i * 256];
        cnt += (v.x > EPSV) + (v.y > EPSV) + (v.z > EPSV) + (v.w > EPSV);
    }
    #pragma unroll
    for (int o = 16; o > 0; o >>= 1) cnt += __shfl_down_sync(0xffffffffu, cnt, o);
    __shared__ int ws[8];
    if ((threadIdx.x & 31) == 0) ws[threadIdx.x >> 5] = cnt;
    __syncthreads();
    if (threadIdx.x == 0) {
        int t = 0;
        #pragma unroll
        for (int w = 0; w < 8; w++) t += ws[w];
        g_d[row] = rsqrtf(1.0f + (float)t);
    }
}

// ---------------------------------------------------------------------------
// K2: g[j][n] = d[j] * sum_k x[j][k] * W[n][k]  (exact fp32).
// Block = 64 j-rows; thread = one output feature n (0..255).
// Writes g_h exact; writes g_gT tf32-rounded, 16-group interleaved:
//   within each 16-group, stored[a*4 + q] = v[a + 4q]  (a=0..3, q=0..3)
// ---------------------------------------------------------------------------
__global__ void __launch_bounds__(256) k2_linear(const float* __restrict__ x,
                                                 const float* __restrict__ W) {
    __shared__ float xs[64 * LDS2];
    __shared__ float wsm[256 * LDS2];
    __shared__ float ds[64];
    int tid = threadIdx.x;
    int j0 = blockIdx.x * 64;
    if (tid < 64) ds[tid] = g_d[j0 + tid];

    float acc[64];
    #pragma unroll
    for (int j = 0; j < 64; j++) acc[j] = 0.0f;

    for (int kc = 0; kc < 8; kc++) {
        int k0 = kc * 32;
        __syncthreads();
        #pragma unroll
        for (int i = 0; i < 8; i++) {
            int e = tid + i * 256;
            int j = e >> 5, k = e & 31;
            xs[j * LDS2 + k] = x[(size_t)(j0 + j) * DF + k0 + k];
        }
        #pragma unroll
        for (int i = 0; i < 32; i++) {
            int e = tid + i * 256;
            int n = e >> 5, k = e & 31;
            wsm[n * LDS2 + k] = W[(size_t)n * DF + k0 + k];
        }
        __syncthreads();
        #pragma unroll
        for (int k4 = 0; k4 < 8; k4++) {
            float4 w4 = *reinterpret_cast<const float4*>(&wsm[tid * LDS2 + k4 * 4]);
            #pragma unroll
            for (int j = 0; j < 64; j++) {
                float4 x4 = *reinterpret_cast<const float4*>(&xs[j * LDS2 + k4 * 4]);
                acc[j] = fmaf(x4.x, w4.x, acc[j]);
                acc[j] = fmaf(x4.y, w4.y, acc[j]);
                acc[j] = fmaf(x4.z, w4.z, acc[j]);
                acc[j] = fmaf(x4.w, w4.w, acc[j]);
            }
        }
    }
    float vals[64];
    #pragma unroll
    for (int j = 0; j < 64; j++) {
        float v = ds[j] * acc[j];
        g_h[(size_t)(j0 + j) * DF + tid] = v;          // exact (for +I term)
        vals[j] = __uint_as_float(f2tf32(v));          // pre-rounded B operand
    }
    // 16-group interleave: stored[a*4+q] = v[a+4q]
    float4* gt = reinterpret_cast<float4*>(g_gT + (size_t)tid * NN + j0);
    #pragma unroll
    for (int q16 = 0; q16 < 4; q16++) {
        const float* v = vals + q16 * 16;
        #pragma unroll
        for (int a = 0; a < 4; a++) {
            float4 w;
            w.x = v[a]; w.y = v[a + 4]; w.z = v[a + 8]; w.w = v[a + 12];
            gt[q16 * 4 + a] = w;
        }
    }
}

// ---------------------------------------------------------------------------
// K3: out[i][c] = relu( d_i * ( sum_j A[i][j] * g[j][c] + g[i][c] ) )
// + writes verbatim A copy from staged smem.
// ---------------------------------------------------------------------------
__device__ __forceinline__ void k3_stage_load(uint32_t sbase, int s,
                                              const float* __restrict__ aSrc,
                                              const float* __restrict__ bSrc,
                                              int tid) {
    uint32_t stA = sbase + (uint32_t)(s * STAGE_FLOATS * 4);
    uint32_t stB = stA + (uint32_t)(A_TILE_FLOATS * 4);
    #pragma unroll
    for (int i = 0; i < 8; i++) {            // A tile: 128 rows x 16 x 16B
        int e = tid + i * 256;
        int r = e >> 4, c = e & 15;
        cp_async16(stA + r * (LDSA * 4) + c * 16, aSrc + (size_t)r * NN + c * 4);
    }
    #pragma unroll
    for (int i = 0; i < 8; i++) {            // B tile: 128 rows x 16 x 16B
        int e = tid + i * 256;
        int r = e >> 4, c = e & 15;
        cp_async16(stB + r * (LDSB * 4) + c * 16, bSrc + (size_t)r * NN + c * 4);
    }
}

__global__ void __launch_bounds__(256, 1) k3_gemm(const float* __restrict__ Aop,
                                                  float* __restrict__ outp,
                                                  float* __restrict__ Acopy) {
    extern __shared__ float smem[];
    uint32_t sbase = smem_u32(smem);
    int tid  = threadIdx.x;
    int lane = tid & 31;
    int wid  = tid >> 5;
    int warp_m = wid >> 2;       // 0..1 -> m offset *64
    int warp_n = wid & 3;        // 0..3 -> n offset *32
    int m0 = blockIdx.x * 128;
    int c0 = blockIdx.y * 128;
    int copy_r0 = blockIdx.y * 64;   // this CTA copies tile rows [copy_r0, +64)

    float acc[4][4][4];
    #pragma unroll
    for (int mi = 0; mi < 4; mi++)
        #pragma unroll
        for (int ni = 0; ni < 4; ni++)
            #pragma unroll
            for (int q = 0; q < 4; q++) acc[mi][ni][q] = 0.0f;

    const float* aBase = Aop  + (size_t)m0 * NN;
    const float* bBase = g_gT + (size_t)c0 * NN;

    // prologue: stages 0..1
    #pragma unroll
    for (int s = 0; s < STAGES - 1; s++) {
        k3_stage_load(sbase, s, aBase + s * BK, bBase + s * BK, tid);
        CP_COMMIT();
    }

    // ldmatrix lane mapping: tiles {rows..+7}, {rows+8..}, {cols+4}, {both}
    int lm_row = ((lane >> 3) & 1) * 8 + (lane & 7);   // 0..15
    int lm_col = (lane >> 4) * 4;                      // 0 or 4 (floats)
    uint32_t a_lm_byte = (uint32_t)(((warp_m * 64 + lm_row) * LDSA + lm_col) * 4);
    // B LDS.128 lane mapping: row = warp_n*32 + (lane>>2), float4 slot = lane&3
    uint32_t b_ld_f = (uint32_t)((warp_n * 32 + (lane >> 2)) * LDSB + (lane & 3) * 4);
    int cp_r = copy_r0 + (tid >> 4);                   // 16 rows per pass
    int cp_c = (tid & 15) * 4;

    for (int kc = 0; kc < NCHUNK; kc++) {
        CP_WAIT1();            // stage kc complete (1 younger group pending)
        __syncthreads();       // (also retires all warps' reads of stage kc-1)
        uint32_t stA = sbase + (uint32_t)((kc % 3) * STAGE_FLOATS * 4);
        const float* As = smem + (kc % 3) * STAGE_FLOATS;
        const float* Bs = As + A_TILE_FLOATS;

        #pragma unroll
        for (int kh = 0; kh < 4; kh++) {       // four 16-k halves
            // one LDS.128 per ni covers both k-steps of this half
            float4 bq[4];
            #pragma unroll
            for (int ni = 0; ni < 4; ni++)
                bq[ni] = *reinterpret_cast<const float4*>(
                    Bs + b_ld_f + ni * 8 * LDSB + kh * 16);
            #pragma unroll
            for (int kj = 0; kj < 2; kj++) {   // kk = kh*2 + kj
                uint32_t af[4][4];
                uint32_t abase = stA + a_lm_byte + (uint32_t)((kh * 2 + kj) * 32);
                #pragma unroll
                for (int mi = 0; mi < 4; mi++)
                    ldsm_x4(af[mi], abase + (uint32_t)(mi * 16 * LDSA * 4));
                #pragma unroll
                for (int mi = 0; mi < 4; mi++)
                    #pragma unroll
                    for (int ni = 0; ni < 4; ni++) {
                        uint32_t bf[2];
                        bf[0] = __float_as_uint(kj ? bq[ni].z : bq[ni].x);
                        bf[1] = __float_as_uint(kj ? bq[ni].w : bq[ni].y);
                        mma_tf32(acc[mi][ni], af[mi], bf);
                    }
            }
        }

        // verbatim A copy from smem (rows [copy_r0, copy_r0+64) of this tile),
        // issued after MMAs so tensor pipe starts first
        #pragma unroll
        for (int it = 0; it < 4; it++) {
            const float* s0 = As + (cp_r + it * 16) * LDSA + cp_c;
            float4 v = *reinterpret_cast<const float4*>(s0);
            *reinterpret_cast<float4*>(
                Acopy + (size_t)(m0 + cp_r + it * 16) * NN + kc * BK + cp_c) = v;
        }

        // single barrier per chunk: next load targets stage (kc+2)%3 ==
        // (kc-1)%3, whose reads all retired before this iteration's barrier
        int kl = kc + STAGES - 1;
        if (kl < NCHUNK)
            k3_stage_load(sbase, kl % 3, aBase + kl * BK, bBase + kl * BK, tid);
        CP_COMMIT();           // empty group at tail keeps accounting aligned
    }

    // epilogue: out = relu(d_i * (acc + g_i))
    #pragma unroll
    for (int mi = 0; mi < 4; mi++) {
        int r0 = m0 + warp_m * 64 + mi * 16 + (lane >> 2);
        int r1 = r0 + 8;
        float d0 = g_d[r0], d1 = g_d[r1];
        #pragma unroll
        for (int ni = 0; ni < 4; ni++) {
            int cc = c0 + warp_n * 32 + ni * 8 + (lane & 3) * 2;
            float2 gh0 = *reinterpret_cast<const float2*>(g_h + (size_t)r0 * DF + cc);
            float2 gh1 = *reinterpret_cast<const float2*>(g_h + (size_t)r1 * DF + cc);
            float2 v0, v1;
            v0.x = fmaxf(d0 * (acc[mi][ni][0] + gh0.x), 0.0f);
            v0.y = fmaxf(d0 * (acc[mi][ni][1] + gh0.y), 0.0f);
            v1.x = fmaxf(d1 * (acc[mi][ni][2] + gh1.x), 0.0f);
            v1.y = fmaxf(d1 * (acc[mi][ni][3] + gh1.y), 0.0f);
            *reinterpret_cast<float2*>(outp + (size_t)r0 * DF + cc) = v0;
            *reinterpret_cast<float2*>(outp + (size_t)r1 * DF + cc) = v1;
        }
    }
}

// ---------------------------------------------------------------------------
// launch
// ---------------------------------------------------------------------------
extern "C" void kernel_launch(void* const* d_in, const int* in_sizes, int n_in,
                              void* d_out, int out_size) {
    (void)in_sizes; (void)n_in; (void)out_size;
    const float* x = (const float*)d_in[0];
    const float* A = (const float*)d_in[1];
    const float* W = (const float*)d_in[2];
    float* out   = (float*)d_out;
    float* Acopy = out + (size_t)NN * DF;

    cudaFuncSetAttribute(k3_gemm, cudaFuncAttributeMaxDynamicSharedMemorySize,
                         SMEM_BYTES);

    k1_deg<<<NN, 256>>>(A);
    k2_linear<<<NN / 64, 256>>>(x, W);
    dim3 g3(NN / 128, DF / 128);
    k3_gemm<<<g3, 256, SMEM_BYTES>>>(A, out, Acopy);
}

// round 11
// speedup vs baseline: 1.1636x; 1.1636x over previous
#include <cuda_runtime.h>
#include <cstdint>

// ---------------------------------------------------------------------------
// GCN layer on GB300 (plain compute_103 PTX -> legacy mma.sync tf32 path):
//   d[i]  = rsqrt(1 + #{j : A[i][j] > 1e-15})
//   g     = diag(d) @ (x @ W^T)                      [8192,256]
//   out   = relu( diag(d) @ (A @ g + g) )            [8192,256]
//   output buffer = [ out (8192*256 f32) | verbatim copy of A (8192^2 f32) ]
//
// k0x/k0w: rna-round x into scratch; round + 16-group-interleave W (B op)
// K1: degrees only (A read once, DRAM roofline)
// K2: tf32 MMA linear (same template as K3), epilogue applies d and emits
//     g_h [j][c] + g_gT [c][j] (via smem transpose, interleaved for K3)
// K3: R8-exact mma.sync tf32 GEMM, 128x128 CTA tile, BK=32, 4-stage
//     cp.async pipe, ldmatrix.x4 A frags (raw f32, HW truncation),
//     verbatim A copy emitted from staged smem tiles.
// ---------------------------------------------------------------------------

#define EPSV 1e-15f

static constexpr int NN = 8192;   // nodes
static constexpr int DF = 256;    // feature dim (in == out)

// shared GEMM tiling (K3 and K2-MMA)
static constexpr int BK = 32;                        // K elems per stage
static constexpr int NCHUNK  = NN / BK;              // 256 (K3)
static constexpr int NCHUNK2 = DF / BK;              // 8   (K2)
static constexpr int STAGES = 4;
static constexpr int LDSA = 36;   // A smem row stride (floats): ldmatrix conflict-free
static constexpr int LDSB = 48;   // B smem row stride (floats): LDS.128 conflict-free
static constexpr int A_TILE_FLOATS = 128 * LDSA;     // 4608
static constexpr int B_TILE_FLOATS = 128 * LDSB;     // 6144
static constexpr int STAGE_FLOATS  = A_TILE_FLOATS + B_TILE_FLOATS;  // 10752
static constexpr int SMEM_BYTES    = STAGES * STAGE_FLOATS * 4;      // 172032
static constexpr int LT = 133;    // K2 transpose buffer stride (133%32=5, conflict-free)

// scratch (static device arrays: allocation-free)
__device__ __align__(128) float g_gT[(size_t)DF * NN];  // tf32-rounded, 16-group interleaved g^T
__device__ __align__(128) float g_h [(size_t)NN * DF];  // g [8192][256] (for +I term)
__device__ __align__(128) float g_xr[(size_t)NN * DF];  // rna-rounded x
__device__ __align__(128) float g_Wr[(size_t)DF * DF];  // rounded + interleaved W [c][k]
__device__ float g_d[NN];

// ---------------------------------------------------------------------------
// PTX helpers (plain sm_80+ PTX only: safe for non-'a' target)
// ---------------------------------------------------------------------------
__device__ __forceinline__ uint32_t smem_u32(const void* p) {
    uint32_t a;
    asm("{ .reg .u64 t; cvta.to.shared.u64 t, %1; cvt.u32.u64 %0, t; }"
        : "=r"(a) : "l"(p));
    return a;
}

__device__ __forceinline__ void cp_async16(uint32_t dst, const void* src) {
    asm volatile("cp.async.cg.shared.global [%0], [%1], 16;"
                 :: "r"(dst), "l"(src));
}
#define CP_COMMIT() asm volatile("cp.async.commit_group;" ::: "memory")
#define CP_WAIT2()  asm volatile("cp.async.wait_group 2;" ::: "memory")

__device__ __forceinline__ uint32_t f2tf32(float f) {
    uint32_t r;
    asm("cvt.rna.tf32.f32 %0, %1;" : "=r"(r) : "f"(f));
    return r;
}
__device__ __forceinline__ float rndf(float f) {
    return __uint_as_float(f2tf32(f));
}

// ldmatrix.x4: four 8x8 b16 tiles == one 16x8 tf32 A fragment {a0,a1,a2,a3}
__device__ __forceinline__ void ldsm_x4(uint32_t* r, uint32_t addr) {
    asm volatile("ldmatrix.sync.aligned.m8n8.x4.shared.b16 {%0,%1,%2,%3}, [%4];"
                 : "=r"(r[0]), "=r"(r[1]), "=r"(r[2]), "=r"(r[3])
                 : "r"(addr));
}

__device__ __forceinline__ void mma_tf32(float* d, const uint32_t* a,
                                         const uint32_t* b) {
    asm volatile(
        "mma.sync.aligned.m16n8k8.row.col.f32.tf32.tf32.f32 "
        "{%0,%1,%2,%3}, {%4,%5,%6,%7}, {%8,%9}, {%0,%1,%2,%3};"
        : "+f"(d[0]), "+f"(d[1]), "+f"(d[2]), "+f"(d[3])
        : "r"(a[0]), "r"(a[1]), "r"(a[2]), "r"(a[3]),
          "r"(b[0]), "r"(b[1]));
}

// ---------------------------------------------------------------------------
// k0x: rna-round x into g_xr (unbiased tf32 operand).
// ---------------------------------------------------------------------------
__global__ void __launch_bounds__(256) k0_round_x(const float* __restrict__ x) {
    size_t i = ((size_t)blockIdx.x * 256 + threadIdx.x) * 8;
    float4 a = *reinterpret_cast<const float4*>(x + i);
    float4 b = *reinterpret_cast<const float4*>(x + i + 4);
    a.x = rndf(a.x); a.y = rndf(a.y); a.z = rndf(a.z); a.w = rndf(a.w);
    b.x = rndf(b.x); b.y = rndf(b.y); b.z = rndf(b.z); b.w = rndf(b.w);
    *reinterpret_cast<float4*>(g_xr + i)     = a;
    *reinterpret_cast<float4*>(g_xr + i + 4) = b;
}

// ---------------------------------------------------------------------------
// k0w: round W + 16-group interleave along k: stored[a*4+q] = v[a+4q].
// One thread per output row c. W is [DOUT][DIN] row-major == [c][k].
// ---------------------------------------------------------------------------
__global__ void __launch_bounds__(32) k0_round_w(const float* __restrict__ W) {
    int c = blockIdx.x * 32 + threadIdx.x;
    const float4* src = reinterpret_cast<const float4*>(W + (size_t)c * DF);
    float4* dst = reinterpret_cast<float4*>(g_Wr + (size_t)c * DF);
    #pragma unroll
    for (int gq = 0; gq < 16; gq++) {
        float v[16];
        #pragma unroll
        for (int t = 0; t < 4; t++) {
            float4 q = src[gq * 4 + t];
            v[t * 4 + 0] = q.x; v[t * 4 + 1] = q.y;
            v[t * 4 + 2] = q.z; v[t * 4 + 3] = q.w;
        }
        #pragma unroll
        for (int a = 0; a < 4; a++) {
            float4 w;
            w.x = rndf(v[a]);     w.y = rndf(v[a + 4]);
            w.z = rndf(v[a + 8]); w.w = rndf(v[a + 12]);
            dst[gq * 4 + a] = w;
        }
    }
}

// ---------------------------------------------------------------------------
// K1: degrees only. One block per row: 256 threads x 8 float4 (read 256 MB).
// ---------------------------------------------------------------------------
__global__ void __launch_bounds__(256) k1_deg(const float* __restrict__ A) {
    int row = blockIdx.x;
    const float4* src = reinterpret_cast<const float4*>(A + (size_t)row * NN);
    int cnt = 0;
    #pragma unroll
    for (int i = 0; i < 8; i++) {
        float4 v = src[threadIdx.x + i * 256];
        cnt += (v.x > EPSV) + (v.y > EPSV) + (v.z > EPSV) + (v.w > EPSV);
    }
    #pragma unroll
    for (int o = 16; o > 0; o >>= 1) cnt += __shfl_down_sync(0xffffffffu, cnt, o);
    __shared__ int ws[8];
    if ((threadIdx.x & 31) == 0) ws[threadIdx.x >> 5] = cnt;
    __syncthreads();
    if (threadIdx.x == 0) {
        int t = 0;
        #pragma unroll
        for (int w = 0; w < 8; w++) t += ws[w];
        g_d[row] = rsqrtf(1.0f + (float)t);
    }
}

// ---------------------------------------------------------------------------
// K2 (tensor): h = x_r @ W_r^T ; g = d .* h.
// Tile 128(j) x 128(c), K=256 in 8 chunks. Same frag scheme as K3.
// Epilogue: g_h[j][c] = d_j*h; smem-transpose -> g_gT[c][j] interleaved+rounded.
// ---------------------------------------------------------------------------
__device__ __forceinline__ void k2_stage_load(uint32_t sbase, int s,
                                              const float* __restrict__ aSrc,
                                              const float* __restrict__ bSrc,
                                              int tid) {
    uint32_t stA = sbase + (uint32_t)(s * STAGE_FLOATS * 4);
    uint32_t stB = stA + (uint32_t)(A_TILE_FLOATS * 4);
    #pragma unroll
    for (int i = 0; i < 4; i++) {            // x tile: 128 rows x 8 x 16B
        int e = tid + i * 256;
        int r = e >> 3, c = e & 7;
        cp_async16(stA + r * (LDSA * 4) + c * 16, aSrc + (size_t)r * DF + c * 4);
    }
    #pragma unroll
    for (int i = 0; i < 4; i++) {            // W tile: 128 rows x 8 x 16B
        int e = tid + i * 256;
        int r = e >> 3, c = e & 7;
        cp_async16(stB + r * (LDSB * 4) + c * 16, bSrc + (size_t)r * DF + c * 4);
    }
}

__global__ void __launch_bounds__(256, 1) k2_mma() {
    extern __shared__ float smem[];
    uint32_t sbase = smem_u32(smem);
    int tid  = threadIdx.x;
    int lane = tid & 31;
    int wid  = tid >> 5;
    int warp_m = wid >> 2;
    int warp_n = wid & 3;
    int m0 = blockIdx.x * 128;   // j
    int c0 = blockIdx.y * 128;   // feature

    float acc[4][4][4];
    #pragma unroll
    for (int mi = 0; mi < 4; mi++)
        #pragma unroll
        for (int ni = 0; ni < 4; ni++)
            #pragma unroll
            for (int q = 0; q < 4; q++) acc[mi][ni][q] = 0.0f;

    const float* aBase = g_xr + (size_t)m0 * DF;
    const float* bBase = g_Wr + (size_t)c0 * DF;

    #pragma unroll
    for (int s = 0; s < STAGES - 1; s++) {
        k2_stage_load(sbase, s, aBase + s * BK, bBase + s * BK, tid);
        CP_COMMIT();
    }

    int lm_row = ((lane >> 3) & 1) * 8 + (lane & 7);
    int lm_col = (lane >> 4) * 4;
    uint32_t a_lm_byte = (uint32_t)(((warp_m * 64 + lm_row) * LDSA + lm_col) * 4);
    uint32_t b_ld_f = (uint32_t)((warp_n * 32 + (lane >> 2)) * LDSB + (lane & 3) * 4);

    for (int kc = 0; kc < NCHUNK2; kc++) {
        CP_WAIT2();
        __syncthreads();
        uint32_t stA = sbase + (uint32_t)((kc & 3) * STAGE_FLOATS * 4);
        const float* Bs = smem + (kc & 3) * STAGE_FLOATS + A_TILE_FLOATS;

        #pragma unroll
        for (int kh = 0; kh < 2; kh++) {
            float4 bq[4];
            #pragma unroll
            for (int ni = 0; ni < 4; ni++)
                bq[ni] = *reinterpret_cast<const float4*>(
                    Bs + b_ld_f + ni * 8 * LDSB + kh * 16);
            #pragma unroll
            for (int kj = 0; kj < 2; kj++) {
                uint32_t af[4][4];
                uint32_t abase = stA + a_lm_byte + (uint32_t)((kh * 2 + kj) * 32);
                #pragma unroll
                for (int mi = 0; mi < 4; mi++)
                    ldsm_x4(af[mi], abase + (uint32_t)(mi * 16 * LDSA * 4));
                #pragma unroll
                for (int mi = 0; mi < 4; mi++)
                    #pragma unroll
                    for (int ni = 0; ni < 4; ni++) {
                        uint32_t bf[2];
                        bf[0] = __float_as_uint(kj ? bq[ni].z : bq[ni].x);
                        bf[1] = __float_as_uint(kj ? bq[ni].w : bq[ni].y);
                        mma_tf32(acc[mi][ni], af[mi], bf);
                    }
            }
        }
        int kl = kc + STAGES - 1;
        if (kl < NCHUNK2)
            k2_stage_load(sbase, kl & 3, aBase + kl * BK, bBase + kl * BK, tid);
        CP_COMMIT();
    }

    // epilogue: apply d, write g_h; transpose via smem; write interleaved g_gT
    __syncthreads();                       // all frag reads retired; reuse smem
    float* tb = smem;                      // [128 c][LT] transpose buffer
    #pragma unroll
    for (int mi = 0; mi < 4; mi++) {
        int r0l = warp_m * 64 + mi * 16 + (lane >> 2);
        int r1l = r0l + 8;
        float d0 = g_d[m0 + r0l], d1 = g_d[m0 + r1l];
        #pragma unroll
        for (int ni = 0; ni < 4; ni++) {
            int ccl = warp_n * 32 + ni * 8 + (lane & 3) * 2;
            float h00 = d0 * acc[mi][ni][0], h01 = d0 * acc[mi][ni][1];
            float h10 = d1 * acc[mi][ni][2], h11 = d1 * acc[mi][ni][3];
            float2 v0; v0.x = h00; v0.y = h01;
            float2 v1; v1.x = h10; v1.y = h11;
            *reinterpret_cast<float2*>(g_h + (size_t)(m0 + r0l) * DF + c0 + ccl) = v0;
            *reinterpret_cast<float2*>(g_h + (size_t)(m0 + r1l) * DF + c0 + ccl) = v1;
            tb[ccl * LT + r0l] = h00; tb[(ccl + 1) * LT + r0l] = h01;
            tb[ccl * LT + r1l] = h10; tb[(ccl + 1) * LT + r1l] = h11;
        }
    }
    __syncthreads();
    // thread t: c-row = t>>1, j-half = t&1 (64 j each = 4 x 16-groups)
    {
        int cl = tid >> 1;
        int jh = (tid & 1) * 64;
        const float* row = tb + cl * LT + jh;
        float4* dst = reinterpret_cast<float4*>(
            g_gT + (size_t)(c0 + cl) * NN + m0 + jh);
        #pragma unroll
        for (int q16 = 0; q16 < 4; q16++) {
            const float* v = row + q16 * 16;
            #pragma unroll
            for (int a = 0; a < 4; a++) {
                float4 w;
                w.x = rndf(v[a]);     w.y = rndf(v[a + 4]);
                w.z = rndf(v[a + 8]); w.w = rndf(v[a + 12]);
                dst[q16 * 4 + a] = w;
            }
        }
    }
}

// ---------------------------------------------------------------------------
// K3: out[i][c] = relu( d_i * ( sum_j A[i][j] * g[j][c] + g[i][c] ) )
// + writes verbatim A copy from staged smem.  (R8-exact)
// ---------------------------------------------------------------------------
__device__ __forceinline__ void k3_stage_load(uint32_t sbase, int s,
                                              const float* __restrict__ aSrc,
                                              const float* __restrict__ bSrc,
                                              int tid) {
    uint32_t stA = sbase + (uint32_t)(s * STAGE_FLOATS * 4);
    uint32_t stB = stA + (uint32_t)(A_TILE_FLOATS * 4);
    #pragma unroll
    for (int i = 0; i < 4; i++) {            // A tile: 128 rows x 8 x 16B
        int e = tid + i * 256;
        int r = e >> 3, c = e & 7;
        cp_async16(stA + r * (LDSA * 4) + c * 16, aSrc + (size_t)r * NN + c * 4);
    }
    #pragma unroll
    for (int i = 0; i < 4; i++) {            // B tile: 128 rows x 8 x 16B
        int e = tid + i * 256;
        int r = e >> 3, c = e & 7;
        cp_async16(stB + r * (LDSB * 4) + c * 16, bSrc + (size_t)r * NN + c * 4);
    }
}

__global__ void __launch_bounds__(256, 1) k3_gemm(const float* __restrict__ Aop,
                                                  float* __restrict__ outp,
                                                  float* __restrict__ Acopy) {
    extern __shared__ float smem[];
    uint32_t sbase = smem_u32(smem);
    int tid  = threadIdx.x;
    int lane = tid & 31;
    int wid  = tid >> 5;
    int warp_m = wid >> 2;
    int warp_n = wid & 3;
    int m0 = blockIdx.x * 128;
    int c0 = blockIdx.y * 128;
    int copy_r0 = blockIdx.y * 64;

    float acc[4][4][4];
    #pragma unroll
    for (int mi = 0; mi < 4; mi++)
        #pragma unroll
        for (int ni = 0; ni < 4; ni++)
            #pragma unroll
            for (int q = 0; q < 4; q++) acc[mi][ni][q] = 0.0f;

    const float* aBase = Aop  + (size_t)m0 * NN;
    const float* bBase = g_gT + (size_t)c0 * NN;

    #pragma unroll
    for (int s = 0; s < STAGES - 1; s++) {
        k3_stage_load(sbase, s, aBase + s * BK, bBase + s * BK, tid);
        CP_COMMIT();
    }

    int lm_row = ((lane >> 3) & 1) * 8 + (lane & 7);
    int lm_col = (lane >> 4) * 4;
    uint32_t a_lm_byte = (uint32_t)(((warp_m * 64 + lm_row) * LDSA + lm_col) * 4);
    uint32_t b_ld_f = (uint32_t)((warp_n * 32 + (lane >> 2)) * LDSB + (lane & 3) * 4);
    int cp_r = copy_r0 + (tid >> 3);
    int cp_c = (tid & 7) * 4;

    for (int kc = 0; kc < NCHUNK; kc++) {
        CP_WAIT2();
        __syncthreads();
        uint32_t stA = sbase + (uint32_t)((kc & 3) * STAGE_FLOATS * 4);
        const float* As = smem + (kc & 3) * STAGE_FLOATS;
        const float* Bs = As + A_TILE_FLOATS;

        // verbatim A copy from smem (rows [copy_r0, copy_r0+64) of this tile)
        {
            float* dst = Acopy + (size_t)(m0 + cp_r) * NN + kc * BK + cp_c;
            const float* s0 = As + (cp_r) * LDSA + cp_c;
            float4 v0 = *reinterpret_cast<const float4*>(s0);
            float4 v1 = *reinterpret_cast<const float4*>(s0 + 32 * LDSA);
            *reinterpret_cast<float4*>(dst) = v0;
            *reinterpret_cast<float4*>(dst + (size_t)32 * NN) = v1;
        }

        #pragma unroll
        for (int kh = 0; kh < 2; kh++) {
            float4 bq[4];
            #pragma unroll
            for (int ni = 0; ni < 4; ni++)
                bq[ni] = *reinterpret_cast<const float4*>(
                    Bs + b_ld_f + ni * 8 * LDSB + kh * 16);
            #pragma unroll
            for (int kj = 0; kj < 2; kj++) {
                uint32_t af[4][4];
                uint32_t abase = stA + a_lm_byte + (uint32_t)((kh * 2 + kj) * 32);
                #pragma unroll
                for (int mi = 0; mi < 4; mi++)
                    ldsm_x4(af[mi], abase + (uint32_t)(mi * 16 * LDSA * 4));
                #pragma unroll
                for (int mi = 0; mi < 4; mi++)
                    #pragma unroll
                    for (int ni = 0; ni < 4; ni++) {
                        uint32_t bf[2];
                        bf[0] = __float_as_uint(kj ? bq[ni].z : bq[ni].x);
                        bf[1] = __float_as_uint(kj ? bq[ni].w : bq[ni].y);
                        mma_tf32(acc[mi][ni], af[mi], bf);
                    }
            }
        }
        int kl = kc + STAGES - 1;
        if (kl < NCHUNK)
            k3_stage_load(sbase, kl & 3, aBase + kl * BK, bBase + kl * BK, tid);
        CP_COMMIT();
    }

    #pragma unroll
    for (int mi = 0; mi < 4; mi++) {
        int r0 = m0 + warp_m * 64 + mi * 16 + (lane >> 2);
        int r1 = r0 + 8;
        float d0 = g_d[r0], d1 = g_d[r1];
        #pragma unroll
        for (int ni = 0; ni < 4; ni++) {
            int cc = c0 + warp_n * 32 + ni * 8 + (lane & 3) * 2;
            float2 gh0 = *reinterpret_cast<const float2*>(g_h + (size_t)r0 * DF + cc);
            float2 gh1 = *reinterpret_cast<const float2*>(g_h + (size_t)r1 * DF + cc);
            float2 v0, v1;
            v0.x = fmaxf(d0 * (acc[mi][ni][0] + gh0.x), 0.0f);
            v0.y = fmaxf(d0 * (acc[mi][ni][1] + gh0.y), 0.0f);
            v1.x = fmaxf(d1 * (acc[mi][ni][2] + gh1.x), 0.0f);
            v1.y = fmaxf(d1 * (acc[mi][ni][3] + gh1.y), 0.0f);
            *reinterpret_cast<float2*>(outp + (size_t)r0 * DF + cc) = v0;
            *reinterpret_cast<float2*>(outp + (size_t)r1 * DF + cc) = v1;
        }
    }
}

// ---------------------------------------------------------------------------
// launch
// ---------------------------------------------------------------------------
extern "C" void kernel_launch(void* const* d_in, const int* in_sizes, int n_in,
                              void* d_out, int out_size) {
    (void)in_sizes; (void)n_in; (void)out_size;
    const float* x = (const float*)d_in[0];
    const float* A = (const float*)d_in[1];
    const float* W = (const float*)d_in[2];
    float* out   = (float*)d_out;
    float* Acopy = out + (size_t)NN * DF;

    cudaFuncSetAttribute(k2_mma, cudaFuncAttributeMaxDynamicSharedMemorySize,
                         SMEM_BYTES);
    cudaFuncSetAttribute(k3_gemm, cudaFuncAttributeMaxDynamicSharedMemorySize,
                         SMEM_BYTES);

    k0_round_x<<<(NN * DF) / (256 * 8), 256>>>(x);
    k0_round_w<<<DF / 32, 32>>>(W);
    k1_deg<<<NN, 256>>>(A);
    dim3 g2(NN / 128, DF / 128);
    k2_mma<<<g2, 256, SMEM_BYTES>>>();
    dim3 g3(NN / 128, DF / 128);
    k3_gemm<<<g3, 256, SMEM_BYTES>>>(A, out, Acopy);
}